// round 11
// baseline (speedup 1.0000x reference)
#include <cuda_runtime.h>
#include <cstdint>

// ---------------------------------------------------------------------------
// DiffractiveLayer_pixel: ifft2(fft2(waves)*h) * gumbel-selected phase/amp,
// then 10x10 pixel expansion (8x8 live center).
//
// All four DFT stages use one transposed-GEMM (W symmetric):
//   T_s[b][n][m] = sum_k T_{s-1}[b][m][k] * Wop[k][n]
// After stage2: T2 = fft2(X) (standard orientation) -> *h epilogue.
// After stage4: T4 = Wc*T2h*Wc (standard orientation) -> *ptrig/S^2 epilogue.
//
// Gumbel/threefry (partitionable layout, jax.random.key(42)) runs on a forked
// side stream, overlapped with stages 1-3; joins before stage 4.
// ---------------------------------------------------------------------------

#define SDIM 200
#define NBATCH 16
#define SS 40000

__device__ float2 g_W[SS];              // DFT matrix, exp(-2*pi*i*f*r/200)
__device__ float2 g_bufA[NBATCH * SS];  // ping
__device__ float2 g_bufB[NBATCH * SS];  // pong
__device__ float2 g_ptrig[SS];          // amp * (cos+isin)

// ------------------------------ threefry2x32 -------------------------------
__host__ __device__ __forceinline__ uint32_t tf_rotl(uint32_t x, int r) {
    return (x << r) | (x >> (32 - r));
}

__host__ __device__ __forceinline__ void threefry2x32(
    uint32_t k0, uint32_t k1, uint32_t x0, uint32_t x1,
    uint32_t& o0, uint32_t& o1)
{
    uint32_t ks2 = k0 ^ k1 ^ 0x1BD11BDAu;
    x0 += k0; x1 += k1;
#define TF_R(r) { x0 += x1; x1 = tf_rotl(x1, r); x1 ^= x0; }
    TF_R(13) TF_R(15) TF_R(26) TF_R(6)   x0 += k1;  x1 += ks2 + 1u;
    TF_R(17) TF_R(29) TF_R(16) TF_R(24)  x0 += ks2; x1 += k0 + 2u;
    TF_R(13) TF_R(15) TF_R(26) TF_R(6)   x0 += k0;  x1 += k1 + 3u;
    TF_R(17) TF_R(29) TF_R(16) TF_R(24)  x0 += k1;  x1 += ks2 + 4u;
    TF_R(13) TF_R(15) TF_R(26) TF_R(6)   x0 += ks2; x1 += k0 + 5u;
#undef TF_R
    o0 = x0; o1 = x1;
}

// ----------------------- FFMA-only accurate logf ---------------------------
__device__ __forceinline__ float flogf(float x) {
    int ix = __float_as_int(x);
    int e = (ix >> 23) - 126;                      // x = m * 2^e, m in [0.5,1)
    float m = __int_as_float((ix & 0x007fffff) | 0x3f000000);
    if (m < 0.70710678f) { m = m + m; e -= 1; }    // m in [sqrt(.5), sqrt(2))
    float f = m - 1.0f;
    float z = f * f;
    float p =            7.0376836292e-2f;
    p = fmaf(p, f, -1.1514610310e-1f);
    p = fmaf(p, f,  1.1676998740e-1f);
    p = fmaf(p, f, -1.2420140846e-1f);
    p = fmaf(p, f,  1.4249322787e-1f);
    p = fmaf(p, f, -1.6668057665e-1f);
    p = fmaf(p, f,  2.0000714765e-1f);
    p = fmaf(p, f, -2.4999993993e-1f);
    p = fmaf(p, f,  3.3333331174e-1f);
    float y = f * z * p;
    float fe = (float)e;
    y = fmaf(fe, -2.12194440e-4f, y);
    y = fmaf(-0.5f, z, y);
    float r = f + y;
    r = fmaf(fe, 0.693359375f, r);
    return r;
}

// bits -> gumbel noise, matching jax.random.uniform(key, ..., 1e-10, 1.0)
__device__ __forceinline__ float gumbel_from_bits(uint32_t bits) {
    float f = __uint_as_float((bits >> 9) | 0x3f800000u) - 1.0f;  // [0,1)
    float u = f + 1e-10f;
    float nl = -flogf(u);
    return -flogf(nl);
}

// ------------------------------- init W ------------------------------------
__global__ void init_W_kernel() {
    int idx = blockIdx.x * 256 + threadIdx.x;
    if (idx < SS) {
        int f = idx / SDIM, r = idx - f * SDIM;
        int k = (f * r) % SDIM;                    // exact integer reduction
        float s, c;
        sincospif(-(float)k * 0.01f, &s, &c);      // angle = -2*pi*k/200
        g_W[idx] = make_float2(c, s);
    }
}

// --------------------------- gumbel argmax ---------------------------------
// Partitionable threefry: element i (row-major over (200,200,256)) draws
// bits = o0 ^ o1 of cipher(key, x0=0, x1=i). One block = one pixel (256 ch).
__global__ void __launch_bounds__(256) gumbel_kernel(
    const float* __restrict__ volt, const float* __restrict__ pf,
    const float* __restrict__ itf,
    uint32_t k1a, uint32_t k1b, uint32_t k2a, uint32_t k2b)
{
    int p = blockIdx.x;           // 0..39999
    int t = threadIdx.x;
    uint32_t i = (uint32_t)(p * 256 + t);

    uint32_t a0, a1, b0, b1;
    threefry2x32(k1a, k1b, 0u, i, a0, a1);   // key1: phase
    threefry2x32(k2a, k2b, 0u, i, b0, b1);   // key2: amplitude

    float v = volt[p * 256 + t];

    float sc[2];
    sc[0] = v + gumbel_from_bits(a0 ^ a1);   // phase score
    sc[1] = v + gumbel_from_bits(b0 ^ b1);   // amplitude score
    int idx[2] = {t, t};

#pragma unroll
    for (int c = 0; c < 2; c++) {
        float vv = sc[c]; int ii = idx[c];
#pragma unroll
        for (int d = 16; d >= 1; d >>= 1) {
            float v2 = __shfl_xor_sync(0xffffffffu, vv, d);
            int   i2 = __shfl_xor_sync(0xffffffffu, ii, d);
            if (v2 > vv || (v2 == vv && i2 < ii)) { vv = v2; ii = i2; }
        }
        sc[c] = vv; idx[c] = ii;
    }

    __shared__ float swv[2][8];
    __shared__ int   swi[2][8];
    int warp = t >> 5;
    if ((t & 31) == 0) {
#pragma unroll
        for (int c = 0; c < 2; c++) { swv[c][warp] = sc[c]; swi[c][warp] = idx[c]; }
    }
    __syncthreads();

    if (t == 0) {
        int win[2];
#pragma unroll
        for (int c = 0; c < 2; c++) {
            float vv = swv[c][0]; int ii = swi[c][0];
#pragma unroll
            for (int w = 1; w < 8; w++) {
                float v2 = swv[c][w]; int i2 = swi[c][w];
                if (v2 > vv || (v2 == vv && i2 < ii)) { vv = v2; ii = i2; }
            }
            win[c] = ii;
        }
        float s, c0;
        float ph = pf[win[0]];
        float amp = itf[win[1]] * 6.0f;
        sincosf(ph, &s, &c0);
        g_ptrig[p] = make_float2(amp * c0, amp * s);
    }
}

// -------------------------- unified DFT stage ------------------------------
// OUT[b][n][m] = sum_k IN[b][m][k] * Wop[k][n]   (transpose-on-write)
// STAGE 1: IN = waves (wr,wi) -> bufB
// STAGE 2: bufB -> bufA, epilogue *= h[n][m]
// STAGE 3: bufA -> bufB, conj(W)
// STAGE 4: bufB -> bufA, conj(W), epilogue *= ptrig[n][m] / S^2
//
// Tiles: 32 merged rows x 40 cols, K-panel 25, 128 threads, grid (5, 100).
template<int STAGE>
__global__ void __launch_bounds__(128) gemm_stage_kernel(
    const float* __restrict__ wr, const float* __restrict__ wi,
    const float* __restrict__ hr, const float* __restrict__ hi)
{
    const float2* __restrict__ IN = (STAGE == 3) ? g_bufA : g_bufB;
    float2* __restrict__ OUT = (STAGE == 1 || STAGE == 3) ? g_bufB : g_bufA;

    __shared__ float2 As[25][32];   // As[kk][rl] = IN[r0+rl][k0+kk]
    __shared__ float2 Ws[25][40];   // Ws[kk][jj] = Wop[k0+kk][j0+jj]

    int tid = threadIdx.x;
    int tc = tid & 7, tr = tid >> 3;     // tc 0..7, tr 0..15
    int j0 = blockIdx.x * 40;            // cols: 5 tiles * 40 = 200
    int r0 = blockIdx.y * 32;            // merged rows: 100 tiles * 32 = 3200

    float2 acc[2][5];
#pragma unroll
    for (int mi = 0; mi < 2; mi++)
#pragma unroll
        for (int ni = 0; ni < 5; ni++) acc[mi][ni] = make_float2(0.f, 0.f);

    for (int k0 = 0; k0 < 200; k0 += 25) {
        for (int t2 = tid; t2 < 32 * 25; t2 += 128) {
            int rl = t2 / 25, kk = t2 - rl * 25;
            int g = (r0 + rl) * 200 + k0 + kk;
            float2 v;
            if (STAGE == 1) { v.x = wr[g]; v.y = wi[g]; } else { v = IN[g]; }
            As[kk][rl] = v;
        }
        for (int t2 = tid; t2 < 25 * 40; t2 += 128) {
            int kk = t2 / 40, jj = t2 - kk * 40;
            float2 w = g_W[(k0 + kk) * 200 + j0 + jj];
            if (STAGE >= 3) w.y = -w.y;
            Ws[kk][jj] = w;
        }
        __syncthreads();
#pragma unroll
        for (int kk = 0; kk < 25; kk++) {
            float2 a[2], w[5];
#pragma unroll
            for (int mi = 0; mi < 2; mi++) a[mi] = As[kk][tr + 16 * mi];
#pragma unroll
            for (int ni = 0; ni < 5; ni++) w[ni] = Ws[kk][tc + 8 * ni];
#pragma unroll
            for (int mi = 0; mi < 2; mi++)
#pragma unroll
                for (int ni = 0; ni < 5; ni++) {
                    acc[mi][ni].x = fmaf(a[mi].x, w[ni].x, acc[mi][ni].x);
                    acc[mi][ni].x = fmaf(-a[mi].y, w[ni].y, acc[mi][ni].x);
                    acc[mi][ni].y = fmaf(a[mi].x, w[ni].y, acc[mi][ni].y);
                    acc[mi][ni].y = fmaf(a[mi].y, w[ni].x, acc[mi][ni].y);
                }
        }
        __syncthreads();
    }

#pragma unroll
    for (int mi = 0; mi < 2; mi++) {
        int rg = r0 + tr + 16 * mi;      // merged row = (b, m)
        int b = rg / 200;
        int m = rg - b * 200;
#pragma unroll
        for (int ni = 0; ni < 5; ni++) {
            int n = j0 + tc + 8 * ni;
            float2 v = acc[mi][ni];
            if (STAGE == 2) {
                float2 hv = make_float2(hr[n * 200 + m], hi[n * 200 + m]);
                float2 t = make_float2(v.x * hv.x - v.y * hv.y,
                                       v.x * hv.y + v.y * hv.x);
                v = t;
            } else if (STAGE == 4) {
                float2 p = g_ptrig[n * 200 + m];
                float2 t = make_float2(v.x * p.x - v.y * p.y,
                                       v.x * p.y + v.y * p.x);
                v = make_float2(t.x * 2.5e-5f, t.y * 2.5e-5f);  // / 200^2
            }
            OUT[b * SS + n * 200 + m] = v;
        }
    }
}

// --------------------------- pixel expansion -------------------------------
// One thread per output float4 (2 complex pixels). Fully coalesced STG.128.
__global__ void __launch_bounds__(256) expand_kernel(float4* __restrict__ out)
{
    unsigned q = blockIdx.x * 256u + threadIdx.x;   // < 32,000,000
    if (q >= 32000000u) return;
    unsigned w = q % 1000u;
    unsigned rowq = q / 1000u;
    unsigned R = rowq % 2000u;
    unsigned b = rowq / 2000u;
    unsigned r = R % 10u;
    unsigned s1 = R / 10u;
    unsigned s2 = w / 5u;
    unsigned pos = w - s2 * 5u;

    float4 v = make_float4(0.f, 0.f, 0.f, 0.f);
    if (r >= 1u && r <= 8u) {
        float2 xv = g_bufA[b * SS + s1 * 200u + s2];
        if (pos == 0u)      v = make_float4(0.f, 0.f, xv.x, xv.y);
        else if (pos == 4u) v = make_float4(xv.x, xv.y, 0.f, 0.f);
        else                v = make_float4(xv.x, xv.y, xv.x, xv.y);
    }
    out[q] = v;
}

// ------------------------------- launcher ----------------------------------
extern "C" void kernel_launch(void* const* d_in, const int* in_sizes, int n_in,
                              void* d_out, int out_size)
{
    (void)in_sizes; (void)n_in; (void)out_size;
    const float* wr   = (const float*)d_in[0];
    const float* wi   = (const float*)d_in[1];
    const float* hr   = (const float*)d_in[2];
    const float* hi   = (const float*)d_in[3];
    const float* volt = (const float*)d_in[4];
    const float* pf   = (const float*)d_in[5];
    const float* itf  = (const float*)d_in[6];
    float4* out = (float4*)d_out;

    // Side stream + events, created once (resources only; per-call work is
    // identical and fully capturable: launches + event record/wait).
    static cudaStream_t s_side = nullptr;
    static cudaEvent_t ev_fork = nullptr, ev_join = nullptr;
    if (s_side == nullptr) {
        cudaStreamCreateWithFlags(&s_side, cudaStreamNonBlocking);
        cudaEventCreateWithFlags(&ev_fork, cudaEventDisableTiming);
        cudaEventCreateWithFlags(&ev_join, cudaEventDisableTiming);
    }

    // jax.random.key(42) = (0,42); partitionable "foldlike" split:
    //   k_i = full cipher pair of threefry((0,42), x0=0, x1=i)
    uint32_t k1a, k1b, k2a, k2b;
    threefry2x32(0u, 42u, 0u, 0u, k1a, k1b);   // k1 (phase)
    threefry2x32(0u, 42u, 0u, 1u, k2a, k2b);   // k2 (amplitude)

    // Fork: gumbel (ALU-bound) overlaps with init_W + stages 1-3 (FMA-bound).
    cudaEventRecord(ev_fork, 0);
    cudaStreamWaitEvent(s_side, ev_fork, 0);
    gumbel_kernel<<<SS, 256, 0, s_side>>>(volt, pf, itf, k1a, k1b, k2a, k2b);
    cudaEventRecord(ev_join, s_side);

    init_W_kernel<<<(SS + 255) / 256, 256>>>();
    gemm_stage_kernel<1><<<dim3(5, 100), 128>>>(wr, wi, hr, hi);  // bufB
    gemm_stage_kernel<2><<<dim3(5, 100), 128>>>(wr, wi, hr, hi);  // bufA (*h)
    gemm_stage_kernel<3><<<dim3(5, 100), 128>>>(wr, wi, hr, hi);  // bufB

    cudaStreamWaitEvent((cudaStream_t)0, ev_join, 0);             // need ptrig
    gemm_stage_kernel<4><<<dim3(5, 100), 128>>>(wr, wi, hr, hi);  // bufA

    expand_kernel<<<(32000000 + 255) / 256, 256>>>(out);
}

// round 16
// speedup vs baseline: 1.5732x; 1.5732x over previous
#include <cuda_runtime.h>
#include <cstdint>

// ---------------------------------------------------------------------------
// DiffractiveLayer_pixel: ifft2(fft2(waves)*h) * gumbel-selected phase/amp,
// then 10x10 pixel expansion (8x8 live center).
//
//   temp = Wc @ ( h ∘ (W @ X @ W) ) @ Wc / S^2      (W = 200x200 DFT matrix)
//   ptrig from threefry/gumbel argmax (partitionable layout, key(42)).
//
// R12: R9 geometry (proven correct/fast) + fma.rn.f32x2 packed complex MACs
// + gumbel merged into stage-1 grid (no streams/events).
// ---------------------------------------------------------------------------

#define SDIM 200
#define NBATCH 16
#define SS 40000

__device__ float2 g_W[SS];              // DFT matrix, exp(-2*pi*i*f*r/200)
__device__ float2 g_bufA[NBATCH * SS];  // ping
__device__ float2 g_bufB[NBATCH * SS];  // pong
__device__ float2 g_ptrig[SS];          // amp * (cos+isin)

typedef unsigned long long ull;

// packed f32x2 helpers (sm_103a FFMA2 path — PTX-only)
#define PACKF2(d, lo, hi) \
    asm("mov.b64 %0, {%1, %2};" : "=l"(d) \
        : "r"(__float_as_uint(lo)), "r"(__float_as_uint(hi)))
#define FMA_F32X2(d, a, b, c) \
    asm("fma.rn.f32x2 %0, %1, %2, %3;" : "=l"(d) : "l"(a), "l"(b), "l"(c))
#define UNPACKF2(lo, hi, s) \
    asm("mov.b64 {%0, %1}, %2;" : "=f"(lo), "=f"(hi) : "l"(s))

__device__ __forceinline__ float fnegf(float x) {
    return __uint_as_float(__float_as_uint(x) ^ 0x80000000u);
}

// ------------------------------ threefry2x32 -------------------------------
__host__ __device__ __forceinline__ uint32_t tf_rotl(uint32_t x, int r) {
    return (x << r) | (x >> (32 - r));
}

__host__ __device__ __forceinline__ void threefry2x32(
    uint32_t k0, uint32_t k1, uint32_t x0, uint32_t x1,
    uint32_t& o0, uint32_t& o1)
{
    uint32_t ks2 = k0 ^ k1 ^ 0x1BD11BDAu;
    x0 += k0; x1 += k1;
#define TF_R(r) { x0 += x1; x1 = tf_rotl(x1, r); x1 ^= x0; }
    TF_R(13) TF_R(15) TF_R(26) TF_R(6)   x0 += k1;  x1 += ks2 + 1u;
    TF_R(17) TF_R(29) TF_R(16) TF_R(24)  x0 += ks2; x1 += k0 + 2u;
    TF_R(13) TF_R(15) TF_R(26) TF_R(6)   x0 += k0;  x1 += k1 + 3u;
    TF_R(17) TF_R(29) TF_R(16) TF_R(24)  x0 += k1;  x1 += ks2 + 4u;
    TF_R(13) TF_R(15) TF_R(26) TF_R(6)   x0 += ks2; x1 += k0 + 5u;
#undef TF_R
    o0 = x0; o1 = x1;
}

// ----------------------- FFMA-only accurate logf ---------------------------
__device__ __forceinline__ float flogf(float x) {
    int ix = __float_as_int(x);
    int e = (ix >> 23) - 126;                      // x = m * 2^e, m in [0.5,1)
    float m = __int_as_float((ix & 0x007fffff) | 0x3f000000);
    if (m < 0.70710678f) { m = m + m; e -= 1; }    // m in [sqrt(.5), sqrt(2))
    float f = m - 1.0f;
    float z = f * f;
    float p =            7.0376836292e-2f;
    p = fmaf(p, f, -1.1514610310e-1f);
    p = fmaf(p, f,  1.1676998740e-1f);
    p = fmaf(p, f, -1.2420140846e-1f);
    p = fmaf(p, f,  1.4249322787e-1f);
    p = fmaf(p, f, -1.6668057665e-1f);
    p = fmaf(p, f,  2.0000714765e-1f);
    p = fmaf(p, f, -2.4999993993e-1f);
    p = fmaf(p, f,  3.3333331174e-1f);
    float y = f * z * p;
    float fe = (float)e;
    y = fmaf(fe, -2.12194440e-4f, y);
    y = fmaf(-0.5f, z, y);
    float r = f + y;
    r = fmaf(fe, 0.693359375f, r);
    return r;
}

// bits -> gumbel noise, matching jax.random.uniform(key, ..., 1e-10, 1.0)
__device__ __forceinline__ float gumbel_from_bits(uint32_t bits) {
    float f = __uint_as_float((bits >> 9) | 0x3f800000u) - 1.0f;  // [0,1)
    float u = f + 1e-10f;
    float nl = -flogf(u);
    return -flogf(nl);
}

// ------------------------------- init W ------------------------------------
__global__ void init_W_kernel() {
    int idx = blockIdx.x * 256 + threadIdx.x;
    if (idx < SS) {
        int f = idx / SDIM, r = idx - f * SDIM;
        int k = (f * r) % SDIM;                    // exact integer reduction
        float s, c;
        sincospif(-(float)k * 0.01f, &s, &c);      // angle = -2*pi*k/200
        g_W[idx] = make_float2(c, s);
    }
}

// ---------------------------- gumbel body ----------------------------------
// Partitionable threefry: element i draws bits = o0^o1 of cipher(key, 0, i).
// One 256-thread block handles one pixel (256 channels).
__device__ __forceinline__ void gumbel_body(
    const float* __restrict__ volt, const float* __restrict__ pf,
    const float* __restrict__ itf,
    uint32_t k1a, uint32_t k1b, uint32_t k2a, uint32_t k2b, int p)
{
    __shared__ float swv[2][8];
    __shared__ int   swi[2][8];

    int t = threadIdx.x;
    uint32_t i = (uint32_t)(p * 256 + t);

    uint32_t a0, a1, b0, b1;
    threefry2x32(k1a, k1b, 0u, i, a0, a1);   // key1: phase
    threefry2x32(k2a, k2b, 0u, i, b0, b1);   // key2: amplitude

    float v = volt[p * 256 + t];

    float sc[2];
    sc[0] = v + gumbel_from_bits(a0 ^ a1);   // phase score
    sc[1] = v + gumbel_from_bits(b0 ^ b1);   // amplitude score
    int idx[2] = {t, t};

#pragma unroll
    for (int c = 0; c < 2; c++) {
        float vv = sc[c]; int ii = idx[c];
#pragma unroll
        for (int d = 16; d >= 1; d >>= 1) {
            float v2 = __shfl_xor_sync(0xffffffffu, vv, d);
            int   i2 = __shfl_xor_sync(0xffffffffu, ii, d);
            if (v2 > vv || (v2 == vv && i2 < ii)) { vv = v2; ii = i2; }
        }
        sc[c] = vv; idx[c] = ii;
    }

    int warp = t >> 5;
    if ((t & 31) == 0) {
#pragma unroll
        for (int c = 0; c < 2; c++) { swv[c][warp] = sc[c]; swi[c][warp] = idx[c]; }
    }
    __syncthreads();

    if (t == 0) {
        int win[2];
#pragma unroll
        for (int c = 0; c < 2; c++) {
            float vv = swv[c][0]; int ii = swi[c][0];
#pragma unroll
            for (int w = 1; w < 8; w++) {
                float v2 = swv[c][w]; int i2 = swi[c][w];
                if (v2 > vv || (v2 == vv && i2 < ii)) { vv = v2; ii = i2; }
            }
            win[c] = ii;
        }
        float s, c0;
        float ph = pf[win[0]];
        float amp = itf[win[1]] * 6.0f;
        sincosf(ph, &s, &c0);
        g_ptrig[p] = make_float2(amp * c0, amp * s);
    }
}

// ------------------------------ LEFT GEMM ----------------------------------
// C[b] = Wop @ X[b].  M=200 (rows of W), merged N=(b,c)=3200, K=200.
// STAGE 1: X from waves (wr,wi), dst g_bufB, no conj.
// STAGE 3: X = g_bufA, dst g_bufB, conj(W).
// 256 threads, tile 40 rows x 64 merged cols, bx in [0,50), by in [0,5).
template<int STAGE>
__device__ __forceinline__ void gemm_left_body(
    const float* __restrict__ wr, const float* __restrict__ wi,
    int bx, int by)
{
    constexpr bool CONJW = (STAGE == 3);
    constexpr bool FROMW = (STAGE == 1);
    const float2* __restrict__ X = g_bufA;
    float2* __restrict__ C = g_bufB;

    __shared__ float2 As[25][40];   // As[kk][i] = Wop[i0+i][k0+kk]
    __shared__ float2 Bs[25][64];   // Bs[kk][jl] = X[b][k0+kk][j]

    int tid = threadIdx.x;
    int tn = tid & 31, tm = tid >> 5;
    int j0 = bx * 64;               // merged columns: 50 tiles * 64 = 3200
    int i0 = by * 40;               // rows: 5 tiles * 40 = 200

    ull acc[5][2];
#pragma unroll
    for (int mi = 0; mi < 5; mi++)
#pragma unroll
        for (int ni = 0; ni < 2; ni++) acc[mi][ni] = 0ull;

    for (int k0 = 0; k0 < 200; k0 += 25) {
        for (int t2 = tid; t2 < 25 * 40; t2 += 256) {
            int i = t2 / 25, kk = t2 - i * 25;
            float2 w = g_W[(i0 + i) * 200 + k0 + kk];
            if (CONJW) w.y = -w.y;
            As[kk][i] = w;
        }
        for (int t2 = tid; t2 < 25 * 64; t2 += 256) {
            int kk = t2 >> 6, jl = t2 & 63;
            int jc = j0 + jl;
            int b = jc / 200;
            int jj = jc - b * 200;
            int g = b * SS + (k0 + kk) * 200 + jj;
            float2 v;
            if (FROMW) { v.x = wr[g]; v.y = wi[g]; } else { v = X[g]; }
            Bs[kk][jl] = v;
        }
        __syncthreads();
#pragma unroll
        for (int kk = 0; kk < 25; kk++) {
            // a side (5 values): keep natural (ax,ay) + swapped (ay,ax)
            // b side (2 values): broadcast packs (bx,bx), (-by,by)
            ull axy[5], ayx[5];
#pragma unroll
            for (int mi = 0; mi < 5; mi++) {
                float2 a = As[kk][tm + 8 * mi];
                PACKF2(axy[mi], a.x, a.y);
                PACKF2(ayx[mi], a.y, a.x);
            }
            ull bx2[2], bny2[2];
#pragma unroll
            for (int ni = 0; ni < 2; ni++) {
                float2 b = Bs[kk][tn + 32 * ni];
                PACKF2(bx2[ni], b.x, b.x);
                PACKF2(bny2[ni], fnegf(b.y), b.y);
            }
#pragma unroll
            for (int mi = 0; mi < 5; mi++)
#pragma unroll
                for (int ni = 0; ni < 2; ni++) {
                    // acc += (b.x*a.x, b.x*a.y) + (-b.y*a.y, b.y*a.x)
                    FMA_F32X2(acc[mi][ni], bx2[ni], axy[mi], acc[mi][ni]);
                    FMA_F32X2(acc[mi][ni], bny2[ni], ayx[mi], acc[mi][ni]);
                }
        }
        __syncthreads();
    }
#pragma unroll
    for (int mi = 0; mi < 5; mi++) {
        int i = i0 + tm + 8 * mi;
#pragma unroll
        for (int ni = 0; ni < 2; ni++) {
            int jc = j0 + tn + 32 * ni;
            int b = jc / 200;
            int jj = jc - b * 200;
            float2 v;
            UNPACKF2(v.x, v.y, acc[mi][ni]);
            C[b * SS + i * 200 + jj] = v;
        }
    }
}

// Stage 1 + gumbel merged: first 250 blocks do the GEMM tile, the remaining
// 40000 blocks each do one gumbel pixel. Different pipes (fma vs alu/shfl)
// co-schedule; gemm CTAs are low blockIdx so they land in wave 1.
__global__ void __launch_bounds__(256) stage1_gumbel_kernel(
    const float* __restrict__ wr, const float* __restrict__ wi,
    const float* __restrict__ volt, const float* __restrict__ pf,
    const float* __restrict__ itf,
    uint32_t k1a, uint32_t k1b, uint32_t k2a, uint32_t k2b)
{
    int bid = blockIdx.x;
    if (bid < 250) {
        gemm_left_body<1>(wr, wi, bid % 50, bid / 50);
    } else {
        gumbel_body(volt, pf, itf, k1a, k1b, k2a, k2b, bid - 250);
    }
}

__global__ void __launch_bounds__(256) gemm_left3_kernel(
    const float* __restrict__ wr, const float* __restrict__ wi)
{
    gemm_left_body<3>(wr, wi, blockIdx.x, blockIdx.y);
}

// ------------------------------ RIGHT GEMM ---------------------------------
// C[b] = X[b] @ Wop.  merged M=(b,i)=3200, N=200, K=200.
// STAGE 2: g_bufB -> g_bufA, no conj, epilogue *= h.
// STAGE 4: g_bufB -> g_bufA, conj(W), epilogue *= ptrig / S^2.
template<int STAGE>
__global__ void __launch_bounds__(256) gemm_right_kernel(
    const float* __restrict__ hr, const float* __restrict__ hi)
{
    constexpr bool CONJW = (STAGE == 4);
    const float2* __restrict__ X = g_bufB;
    float2* __restrict__ C = g_bufA;

    __shared__ float2 Xs[25][64];   // Xs[kk][rl] = X[(r0+rl)][k0+kk]
    __shared__ float2 Ws[25][40];   // Ws[kk][j]  = Wop[k0+kk][j0+j]

    int tid = threadIdx.x;
    int tc = tid & 7, tr = tid >> 3;
    int j0 = blockIdx.x * 40;       // cols: 5 tiles * 40 = 200
    int r0 = blockIdx.y * 64;       // merged rows: 50 tiles * 64 = 3200

    ull acc[2][5];
#pragma unroll
    for (int mi = 0; mi < 2; mi++)
#pragma unroll
        for (int ni = 0; ni < 5; ni++) acc[mi][ni] = 0ull;

    for (int k0 = 0; k0 < 200; k0 += 25) {
        for (int t2 = tid; t2 < 64 * 25; t2 += 256) {
            int rl = t2 / 25, kk = t2 - rl * 25;
            Xs[kk][rl] = X[(r0 + rl) * 200 + k0 + kk];
        }
        for (int t2 = tid; t2 < 25 * 40; t2 += 256) {
            int kk = t2 / 40, jj = t2 - kk * 40;
            float2 w = g_W[(k0 + kk) * 200 + j0 + jj];
            if (CONJW) w.y = -w.y;
            Ws[kk][jj] = w;
        }
        __syncthreads();
#pragma unroll
        for (int kk = 0; kk < 25; kk++) {
            // x side (2 values): broadcast packs; w side (5): natural + swap
            ull xx2[2], xny2[2];
#pragma unroll
            for (int mi = 0; mi < 2; mi++) {
                float2 x = Xs[kk][tr + 32 * mi];
                PACKF2(xx2[mi], x.x, x.x);
                PACKF2(xny2[mi], fnegf(x.y), x.y);
            }
            ull wxy[5], wyx[5];
#pragma unroll
            for (int ni = 0; ni < 5; ni++) {
                float2 w = Ws[kk][tc + 8 * ni];
                PACKF2(wxy[ni], w.x, w.y);
                PACKF2(wyx[ni], w.y, w.x);
            }
#pragma unroll
            for (int mi = 0; mi < 2; mi++)
#pragma unroll
                for (int ni = 0; ni < 5; ni++) {
                    // acc += (x.x*w.x, x.x*w.y) + (-x.y*w.y, x.y*w.x)
                    FMA_F32X2(acc[mi][ni], xx2[mi], wxy[ni], acc[mi][ni]);
                    FMA_F32X2(acc[mi][ni], xny2[mi], wyx[ni], acc[mi][ni]);
                }
        }
        __syncthreads();
    }
#pragma unroll
    for (int mi = 0; mi < 2; mi++) {
        int rg = r0 + tr + 32 * mi;
        int i = rg % 200;
#pragma unroll
        for (int ni = 0; ni < 5; ni++) {
            int jj = j0 + tc + 8 * ni;
            float2 v;
            UNPACKF2(v.x, v.y, acc[mi][ni]);
            if (STAGE == 2) {
                float2 hv = make_float2(hr[i * 200 + jj], hi[i * 200 + jj]);
                v = make_float2(v.x * hv.x - v.y * hv.y,
                                v.x * hv.y + v.y * hv.x);
            } else {
                float2 p = g_ptrig[i * 200 + jj];
                float2 w = make_float2(v.x * p.x - v.y * p.y,
                                       v.x * p.y + v.y * p.x);
                v = make_float2(w.x * 2.5e-5f, w.y * 2.5e-5f);  // / 200^2
            }
            C[rg * 200 + jj] = v;
        }
    }
}

// --------------------------- pixel expansion -------------------------------
// One thread per output float4 (2 complex pixels). Fully coalesced STG.128.
__global__ void __launch_bounds__(256) expand_kernel(float4* __restrict__ out)
{
    unsigned q = blockIdx.x * 256u + threadIdx.x;   // < 32,000,000
    if (q >= 32000000u) return;
    unsigned w = q % 1000u;
    unsigned rowq = q / 1000u;
    unsigned R = rowq % 2000u;
    unsigned b = rowq / 2000u;
    unsigned r = R % 10u;
    unsigned s1 = R / 10u;
    unsigned s2 = w / 5u;
    unsigned pos = w - s2 * 5u;

    float4 v = make_float4(0.f, 0.f, 0.f, 0.f);
    if (r >= 1u && r <= 8u) {
        float2 xv = g_bufA[b * SS + s1 * 200u + s2];
        if (pos == 0u)      v = make_float4(0.f, 0.f, xv.x, xv.y);
        else if (pos == 4u) v = make_float4(xv.x, xv.y, 0.f, 0.f);
        else                v = make_float4(xv.x, xv.y, xv.x, xv.y);
    }
    out[q] = v;
}

// ------------------------------- launcher ----------------------------------
extern "C" void kernel_launch(void* const* d_in, const int* in_sizes, int n_in,
                              void* d_out, int out_size)
{
    (void)in_sizes; (void)n_in; (void)out_size;
    const float* wr   = (const float*)d_in[0];
    const float* wi   = (const float*)d_in[1];
    const float* hr   = (const float*)d_in[2];
    const float* hi   = (const float*)d_in[3];
    const float* volt = (const float*)d_in[4];
    const float* pf   = (const float*)d_in[5];
    const float* itf  = (const float*)d_in[6];
    float4* out = (float4*)d_out;

    // jax.random.key(42) = (0,42); partitionable "foldlike" split:
    //   k_i = full cipher pair of threefry((0,42), x0=0, x1=i)
    uint32_t k1a, k1b, k2a, k2b;
    threefry2x32(0u, 42u, 0u, 0u, k1a, k1b);   // k1 (phase)
    threefry2x32(0u, 42u, 0u, 1u, k2a, k2b);   // k2 (amplitude)

    init_W_kernel<<<(SS + 255) / 256, 256>>>();

    // stage 1 GEMM (250 CTAs) + 40000 gumbel CTAs in one grid
    stage1_gumbel_kernel<<<250 + SS, 256>>>(wr, wi, volt, pf, itf,
                                            k1a, k1b, k2a, k2b);

    gemm_right_kernel<2><<<dim3(5, 50), 256>>>(hr, hi);  // bufA = (bufB@W)*h
    gemm_left3_kernel<<<dim3(50, 5), 256>>>(wr, wi);     // bufB = Wc @ bufA
    gemm_right_kernel<4><<<dim3(5, 50), 256>>>(hr, hi);  // bufA = bufB@Wc *ptrig/S^2

    expand_kernel<<<(32000000 + 255) / 256, 256>>>(out);
}